// round 5
// baseline (speedup 1.0000x reference)
#include <cuda_runtime.h>
#include <cuda_bf16.h>
#include <cstdint>
#include <math.h>

#define BB 16
#define CC 128
#define TT 16384
#define KSPLIT 16
#define KRANGE (TT / KSPLIT)      // 1024 floats per CTA K-range
#define KT 64                     // K per smem tile (64 bf16 = 128B rows)
#define NKT (KRANGE / KT)         // 16 tiles
#define NG 3
#define NJOBS (BB * NG * KSPLIT)  // 768 CTAs

#define TILE_BYTES 16384          // 128 rows x 64 bf16
#define STAGE_BYTES 32768         // A + B tile
#define DYN_SMEM 65536            // 2 stages

// Scratch (no device allocations allowed -> globals)
__device__ float g_gram[(size_t)KSPLIT * BB * NG * CC * CC];   // 50 MB partials
__device__ float g_inv[2 * BB * CC];                           // [0]=inv_s, [2048]=inv_t
__device__ float g_psum[192];

__device__ __forceinline__ uint32_t smem_u32(const void* p) {
    return (uint32_t)__cvta_generic_to_shared(p);
}
__device__ __forceinline__ uint32_t swz(uint32_t off) {
    return off ^ ((off >> 3) & 0x70);   // SW128
}
__device__ __forceinline__ void ldsm4(uint32_t& r0, uint32_t& r1, uint32_t& r2,
                                      uint32_t& r3, uint32_t addr) {
    asm volatile("ldmatrix.sync.aligned.m8n8.x4.shared.b16 {%0,%1,%2,%3}, [%4];"
                 : "=r"(r0), "=r"(r1), "=r"(r2), "=r"(r3) : "r"(addr));
}
__device__ __forceinline__ void mma16816(float* c, const uint32_t* a,
                                         uint32_t b0, uint32_t b1) {
    asm volatile(
        "mma.sync.aligned.m16n8k16.row.col.f32.bf16.bf16.f32 "
        "{%0,%1,%2,%3}, {%4,%5,%6,%7}, {%8,%9}, {%0,%1,%2,%3};"
        : "+f"(c[0]), "+f"(c[1]), "+f"(c[2]), "+f"(c[3])
        : "r"(a[0]), "r"(a[1]), "r"(a[2]), "r"(a[3]), "r"(b0), "r"(b1));
}
__device__ __forceinline__ uint2 cvt_bf16x4(float4 v) {
    __nv_bfloat162 lo = __floats2bfloat162_rn(v.x, v.y);
    __nv_bfloat162 hi = __floats2bfloat162_rn(v.z, v.w);
    return make_uint2(*(uint32_t*)&lo, *(uint32_t*)&hi);
}

// ---------------------------------------------------------------------------
// Gram kernel: one CTA per (b, gram, ksplit). 256 threads = 8 warps.
// Warp-specialized: warps 0-3 = consumers (64x64 warp tile each, 2x2 over the
// 128x128 output), warps 4-7 = producers (LDG -> cvt -> STS, double buffer).
// ---------------------------------------------------------------------------
extern "C" __global__ void __launch_bounds__(256)
gram_kernel(const float* __restrict__ fs, const float* __restrict__ ft) {
    extern __shared__ char smem[];
    const uint32_t smb = smem_u32(smem);

    int bx  = blockIdx.x;
    int b   = bx / (NG * KSPLIT);
    int rem = bx % (NG * KSPLIT);
    int g   = rem / KSPLIT;
    int ks  = rem % KSPLIT;
    bool dual = (g == 2);

    const float* Am = (g == 0) ? ft : fs;
    const float* Bm = (g == 1) ? fs : ft;

    int tid  = threadIdx.x;
    int wid  = tid >> 5;
    int lane = tid & 31;
    bool producer = (wid >= 4);

    // ---- consumer mapping: warp tile 64x64, wm = wid&1 rows, wn = wid>>1 cols
    int wm   = wid & 1;
    int wn   = (wid >> 1) & 1;
    int gid  = lane >> 2;
    int tid4 = lane & 3;
    uint32_t a_row  = (uint32_t)(wm * 64 + (lane & 15));
    uint32_t a_koff = (uint32_t)((lane >> 4) * 16);
    uint32_t b_rowbase = (uint32_t)(wn * 64 + ((lane >> 4) << 3) + (lane & 7));
    uint32_t b_koff = (uint32_t)(((lane >> 3) & 1) * 16);

    // ---- producer mapping: 128 threads cover a 32KB tile; 16 threads per
    // 256B row segment; thread loads 16 float4 (rows lrow0 + i*8).
    int pid   = tid & 127;
    int lcol  = pid & 15;
    int lrow0 = pid >> 4;        // 0..7
    const float* baseA = Am + (size_t)b * CC * TT + ks * KRANGE + (size_t)lcol * 4;
    const float* baseB = Bm + (size_t)b * CC * TT + ks * KRANGE + (size_t)lcol * 4;

    float acc[4][8][4];
#pragma unroll
    for (int mi = 0; mi < 4; mi++)
#pragma unroll
        for (int ni = 0; ni < 8; ni++)
#pragma unroll
            for (int q = 0; q < 4; q++) acc[mi][ni][q] = 0.f;

    // ---- prologue: producers fill tile 0 into buf 0 ----
    if (producer) {
        float4 va[16], vb[16];
#pragma unroll
        for (int i = 0; i < 16; i++)
            va[i] = *(const float4*)(baseA + (size_t)(lrow0 + i * 8) * TT);
        if (dual) {
#pragma unroll
            for (int i = 0; i < 16; i++)
                vb[i] = *(const float4*)(baseB + (size_t)(lrow0 + i * 8) * TT);
        }
#pragma unroll
        for (int i = 0; i < 16; i++) {
            uint32_t so = swz((uint32_t)(lrow0 + i * 8) * 128 + lcol * 8);
            *(uint2*)(smem + so) = cvt_bf16x4(va[i]);
        }
        if (dual) {
#pragma unroll
            for (int i = 0; i < 16; i++) {
                uint32_t so = swz((uint32_t)(lrow0 + i * 8) * 128 + lcol * 8);
                *(uint2*)(smem + TILE_BYTES + so) = cvt_bf16x4(vb[i]);
            }
        }
    }
    __syncthreads();

    for (int kt = 0; kt < NKT; kt++) {
        int cur = kt & 1;
        int nxt = cur ^ 1;

        if (producer) {
            // load + convert + store tile kt+1 into buf nxt; the gmem stall
            // here is hidden behind consumer compute (barrier decouples).
            if (kt + 1 < NKT) {
                const float* pA = baseA + (size_t)(kt + 1) * KT;
                float4 va[16], vb[16];
#pragma unroll
                for (int i = 0; i < 16; i++)
                    va[i] = *(const float4*)(pA + (size_t)(lrow0 + i * 8) * TT);
                if (dual) {
                    const float* pB = baseB + (size_t)(kt + 1) * KT;
#pragma unroll
                    for (int i = 0; i < 16; i++)
                        vb[i] = *(const float4*)(pB + (size_t)(lrow0 + i * 8) * TT);
                }
                char* sdst = smem + nxt * STAGE_BYTES;
#pragma unroll
                for (int i = 0; i < 16; i++) {
                    uint32_t so = swz((uint32_t)(lrow0 + i * 8) * 128 + lcol * 8);
                    *(uint2*)(sdst + so) = cvt_bf16x4(va[i]);
                }
                if (dual) {
#pragma unroll
                    for (int i = 0; i < 16; i++) {
                        uint32_t so = swz((uint32_t)(lrow0 + i * 8) * 128 + lcol * 8);
                        *(uint2*)(sdst + TILE_BYTES + so) = cvt_bf16x4(vb[i]);
                    }
                }
            }
        } else {
            // consumers: 4 k16 steps from buffer cur
            uint32_t abase = smb + cur * STAGE_BYTES;
            uint32_t bbase = abase + (dual ? TILE_BYTES : 0);
#pragma unroll
            for (int kc = 0; kc < 4; kc++) {
                uint32_t kb = (uint32_t)(kc * 32);
                uint32_t afr[4][4];
#pragma unroll
                for (int mi = 0; mi < 4; mi++) {
                    uint32_t addr = abase + swz((a_row + mi * 16) * 128 + kb + a_koff);
                    ldsm4(afr[mi][0], afr[mi][1], afr[mi][2], afr[mi][3], addr);
                }
#pragma unroll
                for (int nb = 0; nb < 4; nb++) {
                    uint32_t r0, r1, r2, r3;
                    uint32_t addr = bbase + swz((b_rowbase + nb * 16) * 128 + kb + b_koff);
                    ldsm4(r0, r1, r2, r3, addr);
#pragma unroll
                    for (int mi = 0; mi < 4; mi++) {
                        mma16816(acc[mi][2 * nb],     afr[mi], r0, r1);
                        mma16816(acc[mi][2 * nb + 1], afr[mi], r2, r3);
                    }
                }
            }
        }
        __syncthreads();
    }

    // ---- epilogue: consumers write partial gram at [i*CC + j] ----
    if (!producer) {
        float* out = g_gram + (((size_t)ks * BB + b) * NG + g) * (CC * CC);
#pragma unroll
        for (int mi = 0; mi < 4; mi++) {
            int r0 = wm * 64 + mi * 16 + gid;
#pragma unroll
            for (int ni = 0; ni < 8; ni++) {
                int c0 = wn * 64 + ni * 8 + tid4 * 2;
                *(float2*)(out + (size_t)r0 * CC + c0) =
                    make_float2(acc[mi][ni][0], acc[mi][ni][1]);
                *(float2*)(out + (size_t)(r0 + 8) * CC + c0) =
                    make_float2(acc[mi][ni][2], acc[mi][ni][3]);
            }
        }
    }
}

// ---------------------------------------------------------------------------
// Norm kernel: inverse norms from full-K gram diagonals. 32 blocks.
// ---------------------------------------------------------------------------
__global__ void norm_kernel() {
    int n = blockIdx.x;
    int b = n >> 1;
    int which = n & 1;
    int gsel = which ? 0 : 1;           // t diag in gram g=0, s in g=1
    int d = threadIdx.x;
    if (d >= CC) return;

    const size_t STRIDE = (size_t)BB * NG * CC * CC;
    const float* base = g_gram + ((size_t)b * NG + gsel) * (CC * CC) + (size_t)d * (CC + 1);
    float v = 0.f;
#pragma unroll
    for (int ks = 0; ks < KSPLIT; ks++) v += base[ks * STRIDE];
    g_inv[which * (BB * CC) + b * CC + d] = rsqrtf(fmaxf(v, 1e-24f));
}

// ---------------------------------------------------------------------------
// Reduce kernel: 192 blocks = (b,g) x 4 row-quarters. Coalesced slices.
// ---------------------------------------------------------------------------
__global__ void reduce_kernel() {
    int blk = blockIdx.x;
    int bg  = blk >> 2;
    int q   = blk & 3;
    int b   = bg / NG;
    int g   = bg % NG;
    int tid = threadIdx.x;

    const float* inv_s = g_inv;
    const float* inv_t = g_inv + BB * CC;
    const float* iA = (g == 0) ? inv_t : inv_s;
    const float* iB = (g == 1) ? inv_s : inv_t;
    float w = (g == 2) ? -2.f : 1.f;

    const size_t STRIDE = (size_t)BB * NG * CC * CC;
    const float* gb = g_gram + ((size_t)b * NG + g) * (CC * CC) + (size_t)q * 32 * CC;

    float lsum = 0.f;
#pragma unroll
    for (int it = 0; it < 4; it++) {
        int e4 = it * 256 + tid;
        float4 v = make_float4(0.f, 0.f, 0.f, 0.f);
#pragma unroll
        for (int ks = 0; ks < KSPLIT; ks++) {
            float4 u = ((const float4*)(gb + ks * STRIDE))[e4];
            v.x += u.x; v.y += u.y; v.z += u.z; v.w += u.w;
        }
        int e = e4 * 4;
        int i = q * 32 + (e >> 7);
        int j = e & 127;
        float ai = iA[b * CC + i];
        float a0 = v.x * ai * iB[b * CC + j];
        float a1 = v.y * ai * iB[b * CC + j + 1];
        float a2 = v.z * ai * iB[b * CC + j + 2];
        float a3 = v.w * ai * iB[b * CC + j + 3];
        lsum += a0 * a0 + a1 * a1 + a2 * a2 + a3 * a3;
    }

    __shared__ float red[256];
    red[tid] = lsum;
    __syncthreads();
    for (int s = 128; s > 0; s >>= 1) {
        if (tid < s) red[tid] += red[tid + s];
        __syncthreads();
    }
    if (tid == 0) g_psum[blk] = w * red[0];
}

__global__ void final_kernel(float* __restrict__ out) {
    __shared__ float red[256];
    float s = (threadIdx.x < 192) ? g_psum[threadIdx.x] : 0.f;
    red[threadIdx.x] = s;
    __syncthreads();
    for (int st = 128; st > 0; st >>= 1) {
        if (threadIdx.x < st) red[threadIdx.x] += red[threadIdx.x + st];
        __syncthreads();
    }
    if (threadIdx.x == 0)
        out[0] = red[0] / (float)(BB * CC * CC);
}

extern "C" void kernel_launch(void* const* d_in, const int* in_sizes, int n_in,
                              void* d_out, int out_size) {
    const float* fs = (const float*)d_in[0];
    const float* ft = (const float*)d_in[1];
    float* out = (float*)d_out;
    (void)in_sizes; (void)n_in; (void)out_size;

    cudaFuncSetAttribute(gram_kernel,
                         cudaFuncAttributeMaxDynamicSharedMemorySize, DYN_SMEM);

    gram_kernel<<<NJOBS, 256, DYN_SMEM>>>(fs, ft);
    norm_kernel<<<2 * BB, 128>>>();
    reduce_kernel<<<192, 256>>>();
    final_kernel<<<1, 256>>>(out);
}

// round 7
// speedup vs baseline: 1.3030x; 1.3030x over previous
#include <cuda_runtime.h>
#include <cuda_bf16.h>
#include <cstdint>
#include <math.h>

#define BB 16
#define CC 128
#define TT 16384
#define KSPLIT 16
#define KRANGE (TT / KSPLIT)      // 1024 floats per CTA K-range
#define KT 64                     // K per smem tile (64 bf16 = 128B rows)
#define NKT (KRANGE / KT)         // 16 tiles
#define NG 3
#define NJOBS (BB * NG * KSPLIT)  // 768 CTAs

#define TILE_BYTES 16384          // 128 rows x 64 bf16
#define STAGE_BYTES 32768         // A + B tile
#define DYN_SMEM 65536            // 2 stages

// Scratch (no device allocations allowed -> globals)
__device__ float g_gram[(size_t)KSPLIT * BB * NG * CC * CC];   // 50 MB partials
__device__ float g_psum[192];
__device__ int   g_counter;       // zero-initialized; reset by last block

__device__ __forceinline__ uint32_t smem_u32(const void* p) {
    return (uint32_t)__cvta_generic_to_shared(p);
}
__device__ __forceinline__ uint32_t swz(uint32_t off) {
    return off ^ ((off >> 3) & 0x70);   // SW128
}
__device__ __forceinline__ void ldsm4(uint32_t& r0, uint32_t& r1, uint32_t& r2,
                                      uint32_t& r3, uint32_t addr) {
    asm volatile("ldmatrix.sync.aligned.m8n8.x4.shared.b16 {%0,%1,%2,%3}, [%4];"
                 : "=r"(r0), "=r"(r1), "=r"(r2), "=r"(r3) : "r"(addr));
}
__device__ __forceinline__ void mma16816(float* c, const uint32_t* a,
                                         uint32_t b0, uint32_t b1) {
    asm volatile(
        "mma.sync.aligned.m16n8k16.row.col.f32.bf16.bf16.f32 "
        "{%0,%1,%2,%3}, {%4,%5,%6,%7}, {%8,%9}, {%0,%1,%2,%3};"
        : "+f"(c[0]), "+f"(c[1]), "+f"(c[2]), "+f"(c[3])
        : "r"(a[0]), "r"(a[1]), "r"(a[2]), "r"(a[3]), "r"(b0), "r"(b1));
}
__device__ __forceinline__ uint2 cvt_bf16x4(float4 v) {
    __nv_bfloat162 lo = __floats2bfloat162_rn(v.x, v.y);
    __nv_bfloat162 hi = __floats2bfloat162_rn(v.z, v.w);
    return make_uint2(*(uint32_t*)&lo, *(uint32_t*)&hi);
}

// ---------------------------------------------------------------------------
// Gram kernel: one CTA per (b, gram, ksplit). 256 threads = 8 warps, each a
// 32x64 output tile. Chunked register prefetch (4 float4 at a time) keeps
// regs <=128 so 2 CTAs co-reside per SM (their non-MMA phases interleave).
// ---------------------------------------------------------------------------
extern "C" __global__ void __launch_bounds__(256, 2)
gram_kernel(const float* __restrict__ fs, const float* __restrict__ ft) {
    extern __shared__ char smem[];
    const uint32_t smb = smem_u32(smem);

    int bx  = blockIdx.x;
    int b   = bx / (NG * KSPLIT);
    int rem = bx % (NG * KSPLIT);
    int g   = rem / KSPLIT;
    int ks  = rem % KSPLIT;
    bool dual = (g == 2);

    const float* Am = (g == 0) ? ft : fs;
    const float* Bm = (g == 1) ? fs : ft;

    int tid  = threadIdx.x;
    int wid  = tid >> 5;
    int lane = tid & 31;
    int wm   = wid & 3;       // m block: 32*wm
    int wn   = wid >> 2;      // n block: 64*wn
    int gid  = lane >> 2;
    int tid4 = lane & 3;

    // Coalesced loader mapping
    int lrow0 = tid >> 4;     // 0..15
    int lcol  = tid & 15;
    const float* baseA = Am + (size_t)b * CC * TT + ks * KRANGE + (size_t)lcol * 4;
    const float* baseB = Bm + (size_t)b * CC * TT + ks * KRANGE + (size_t)lcol * 4;

    // ldmatrix lane addresses
    uint32_t a_row  = (uint32_t)(wm * 32 + (lane & 15));
    uint32_t a_koff = (uint32_t)((lane >> 4) * 16);
    uint32_t b_rowbase = (uint32_t)(wn * 64 + ((lane >> 4) << 3) + (lane & 7));
    uint32_t b_koff = (uint32_t)(((lane >> 3) & 1) * 16);

    float acc[2][8][4];
#pragma unroll
    for (int mi = 0; mi < 2; mi++)
#pragma unroll
        for (int ni = 0; ni < 8; ni++)
#pragma unroll
            for (int q = 0; q < 4; q++) acc[mi][ni][q] = 0.f;

    // ---- prologue: tile 0 (chunked to limit live registers) ----
#pragma unroll
    for (int h = 0; h < 2; h++) {
        float4 va[4], vb[4];
#pragma unroll
        for (int i = 0; i < 4; i++)
            va[i] = *(const float4*)(baseA + (size_t)(lrow0 + (h * 4 + i) * 16) * TT);
        if (dual) {
#pragma unroll
            for (int i = 0; i < 4; i++)
                vb[i] = *(const float4*)(baseB + (size_t)(lrow0 + (h * 4 + i) * 16) * TT);
        }
#pragma unroll
        for (int i = 0; i < 4; i++) {
            uint32_t so = swz((uint32_t)(lrow0 + (h * 4 + i) * 16) * 128 + lcol * 8);
            *(uint2*)(smem + so) = cvt_bf16x4(va[i]);
        }
        if (dual) {
#pragma unroll
            for (int i = 0; i < 4; i++) {
                uint32_t so = swz((uint32_t)(lrow0 + (h * 4 + i) * 16) * 128 + lcol * 8);
                *(uint2*)(smem + TILE_BYTES + so) = cvt_bf16x4(vb[i]);
            }
        }
    }
    __syncthreads();

    for (int kt = 0; kt < NKT; kt++) {
        int cur = kt & 1;
        int nxt = cur ^ 1;
        bool pf = (kt + 1 < NKT);
        const float* pA = baseA + (size_t)(kt + 1) * KT;
        const float* pB = baseB + (size_t)(kt + 1) * KT;
        char* sdst = smem + nxt * STAGE_BYTES;

        uint32_t abase = smb + cur * STAGE_BYTES;
        uint32_t bbase = abase + (dual ? TILE_BYTES : 0);

#pragma unroll
        for (int h = 0; h < 2; h++) {
            // issue chunk-h loads of next tile
            float4 va[4], vb[4];
            if (pf) {
#pragma unroll
                for (int i = 0; i < 4; i++)
                    va[i] = *(const float4*)(pA + (size_t)(lrow0 + (h * 4 + i) * 16) * TT);
                if (dual) {
#pragma unroll
                    for (int i = 0; i < 4; i++)
                        vb[i] = *(const float4*)(pB + (size_t)(lrow0 + (h * 4 + i) * 16) * TT);
                }
            }

            // compute 2 k16 steps (hides the chunk load latency)
#pragma unroll
            for (int kc = h * 2; kc < h * 2 + 2; kc++) {
                uint32_t kb = (uint32_t)(kc * 32);
                uint32_t afr[2][4];
#pragma unroll
                for (int mi = 0; mi < 2; mi++) {
                    uint32_t addr = abase + swz((a_row + mi * 16) * 128 + kb + a_koff);
                    ldsm4(afr[mi][0], afr[mi][1], afr[mi][2], afr[mi][3], addr);
                }
#pragma unroll
                for (int nb = 0; nb < 4; nb++) {
                    uint32_t r0, r1, r2, r3;
                    uint32_t addr = bbase + swz((b_rowbase + nb * 16) * 128 + kb + b_koff);
                    ldsm4(r0, r1, r2, r3, addr);
                    mma16816(acc[0][2 * nb],     afr[0], r0, r1);
                    mma16816(acc[0][2 * nb + 1], afr[0], r2, r3);
                    mma16816(acc[1][2 * nb],     afr[1], r0, r1);
                    mma16816(acc[1][2 * nb + 1], afr[1], r2, r3);
                }
            }

            // convert + store chunk h
            if (pf) {
#pragma unroll
                for (int i = 0; i < 4; i++) {
                    uint32_t so = swz((uint32_t)(lrow0 + (h * 4 + i) * 16) * 128 + lcol * 8);
                    *(uint2*)(sdst + so) = cvt_bf16x4(va[i]);
                }
                if (dual) {
#pragma unroll
                    for (int i = 0; i < 4; i++) {
                        uint32_t so = swz((uint32_t)(lrow0 + (h * 4 + i) * 16) * 128 + lcol * 8);
                        *(uint2*)(sdst + TILE_BYTES + so) = cvt_bf16x4(vb[i]);
                    }
                }
            }
        }
        __syncthreads();
    }

    // ---- epilogue: partial gram at [i*CC + j] ----
    float* out = g_gram + (((size_t)ks * BB + b) * NG + g) * (CC * CC);
#pragma unroll
    for (int mi = 0; mi < 2; mi++) {
        int r0 = wm * 32 + mi * 16 + gid;
#pragma unroll
        for (int ni = 0; ni < 8; ni++) {
            int c0 = wn * 64 + ni * 8 + tid4 * 2;
            *(float2*)(out + (size_t)r0 * CC + c0) =
                make_float2(acc[mi][ni][0], acc[mi][ni][1]);
            *(float2*)(out + (size_t)(r0 + 8) * CC + c0) =
                make_float2(acc[mi][ni][2], acc[mi][ni][3]);
        }
    }
}

// ---------------------------------------------------------------------------
// Fused tail: 192 blocks = (b,g) x 4 row-quarters.
// Each block derives the inverse norms it needs from full-K gram diagonals,
// reduces its quarter, then the LAST block combines all partials (fixed
// order -> deterministic) and writes the scalar. Counter self-resets.
// ---------------------------------------------------------------------------
__global__ void tail_kernel(float* __restrict__ out) {
    int blk = blockIdx.x;
    int bg  = blk >> 2;
    int q   = blk & 3;
    int b   = bg / NG;
    int g   = bg % NG;
    int tid = threadIdx.x;

    const size_t STRIDE = (size_t)BB * NG * CC * CC;
    __shared__ float iA_s[32];    // A-side inv norms for rows q*32..q*32+31
    __shared__ float iB_s[CC];    // B-side inv norms, all 128 cols

    // diag sources: matrix s -> gram g=1 diag, matrix t -> gram g=0 diag
    int gselA = (g == 0) ? 0 : 1;
    int gselB = (g == 1) ? 1 : 0;

    if (tid < 32) {
        int d = q * 32 + tid;
        const float* base = g_gram + ((size_t)b * NG + gselA) * (CC * CC) + (size_t)d * (CC + 1);
        float v = 0.f;
#pragma unroll
        for (int ks = 0; ks < KSPLIT; ks++) v += base[ks * STRIDE];
        iA_s[tid] = rsqrtf(fmaxf(v, 1e-24f));
    } else if (tid < 32 + CC) {
        int d = tid - 32;
        const float* base = g_gram + ((size_t)b * NG + gselB) * (CC * CC) + (size_t)d * (CC + 1);
        float v = 0.f;
#pragma unroll
        for (int ks = 0; ks < KSPLIT; ks++) v += base[ks * STRIDE];
        iB_s[d] = rsqrtf(fmaxf(v, 1e-24f));
    }
    __syncthreads();

    float w = (g == 2) ? -2.f : 1.f;
    const float* gb = g_gram + ((size_t)b * NG + g) * (CC * CC) + (size_t)q * 32 * CC;

    float lsum = 0.f;
#pragma unroll
    for (int it = 0; it < 4; it++) {
        int e4 = it * 256 + tid;
        float4 v = make_float4(0.f, 0.f, 0.f, 0.f);
#pragma unroll
        for (int ks = 0; ks < KSPLIT; ks++) {
            float4 u = ((const float4*)(gb + ks * STRIDE))[e4];
            v.x += u.x; v.y += u.y; v.z += u.z; v.w += u.w;
        }
        int e = e4 * 4;
        int i = e >> 7;          // local row 0..31
        int j = e & 127;
        float ai = iA_s[i];
        float a0 = v.x * ai * iB_s[j];
        float a1 = v.y * ai * iB_s[j + 1];
        float a2 = v.z * ai * iB_s[j + 2];
        float a3 = v.w * ai * iB_s[j + 3];
        lsum += a0 * a0 + a1 * a1 + a2 * a2 + a3 * a3;
    }

    __shared__ float red[256];
    red[tid] = lsum;
    __syncthreads();
    for (int s = 128; s > 0; s >>= 1) {
        if (tid < s) red[tid] += red[tid + s];
        __syncthreads();
    }

    __shared__ bool is_last;
    if (tid == 0) {
        g_psum[blk] = w * red[0];
        __threadfence();
        int old = atomicAdd(&g_counter, 1);
        is_last = (old == 191);
    }
    __syncthreads();

    if (is_last) {
        __threadfence();
        float s = (tid < 192) ? g_psum[tid] : 0.f;
        red[tid] = s;
        __syncthreads();
        for (int st = 128; st > 0; st >>= 1) {
            if (tid < st) red[tid] += red[tid + st];
            __syncthreads();
        }
        if (tid == 0) {
            out[0] = red[0] / (float)(BB * CC * CC);
            g_counter = 0;    // reset for next graph replay
        }
    }
}

extern "C" void kernel_launch(void* const* d_in, const int* in_sizes, int n_in,
                              void* d_out, int out_size) {
    const float* fs = (const float*)d_in[0];
    const float* ft = (const float*)d_in[1];
    float* out = (float*)d_out;
    (void)in_sizes; (void)n_in; (void)out_size;

    cudaFuncSetAttribute(gram_kernel,
                         cudaFuncAttributeMaxDynamicSharedMemorySize, DYN_SMEM);

    gram_kernel<<<NJOBS, 256, DYN_SMEM>>>(fs, ft);
    tail_kernel<<<192, 256>>>(out);
}